// round 1
// baseline (speedup 1.0000x reference)
#include <cuda_runtime.h>
#include <math.h>

#define Bn 4
#define Sn 512
#define Dn 512
#define Hn 8
#define DKn 64
#define NTAB 33

// Scratch (no allocations allowed -> __device__ globals)
__device__ float g_q[Bn*Hn*Sn*DKn];
__device__ float g_k[Bn*Hn*Sn*DKn];
__device__ float g_v[Bn*Hn*Sn*DKn];
__device__ float g_ctx[(size_t)Bn*Sn*Dn];
__device__ float g_out[(size_t)Bn*Sn*Dn];

// ---------------------------------------------------------------------------
// Generic GEMM: C[row,col] = sum_k A[row,k] * W[col,k] + bias[col]
// mode 0/1/2: output to g_q/g_k/g_v in [B,H,S,DK] layout
// mode 3:     A = g_ctx (arg A ignored), output plain [row,col] to g_out
// 64x64 tile, k-chunk 32, 256 threads, 4x4 per thread, k-major smem (float4 LDS)
// ---------------------------------------------------------------------------
__global__ __launch_bounds__(256) void gemm_kernel(const float* __restrict__ A,
                                                   const float* __restrict__ W,
                                                   const float* __restrict__ bias,
                                                   int mode)
{
    __shared__ __align__(16) float As[32][68];
    __shared__ __align__(16) float Ws[32][68];
    const float* Ap = (mode == 3) ? g_ctx : A;
    float* outp = (mode == 0) ? g_q : (mode == 1) ? g_k : (mode == 2) ? g_v : g_out;

    int tid = threadIdx.x;
    int tx = tid & 15, ty = tid >> 4;
    int col0 = blockIdx.x * 64;
    int row0 = blockIdx.y * 64;

    float acc[4][4] = {};
    for (int k0 = 0; k0 < Dn; k0 += 32) {
#pragma unroll
        for (int l = 0; l < 8; l++) {
            int lin = tid + l * 256;
            int i = lin >> 5, kk = lin & 31;
            As[kk][i] = Ap[(size_t)(row0 + i) * Dn + k0 + kk];
            Ws[kk][i] = W[(size_t)(col0 + i) * Dn + k0 + kk];
        }
        __syncthreads();
#pragma unroll
        for (int kk = 0; kk < 32; kk++) {
            float4 a = *(const float4*)&As[kk][ty * 4];
            float4 w = *(const float4*)&Ws[kk][tx * 4];
            float av[4] = {a.x, a.y, a.z, a.w};
            float wv[4] = {w.x, w.y, w.z, w.w};
#pragma unroll
            for (int r = 0; r < 4; r++)
#pragma unroll
                for (int c = 0; c < 4; c++)
                    acc[r][c] += av[r] * wv[c];
        }
        __syncthreads();
    }
#pragma unroll
    for (int r = 0; r < 4; r++) {
        int row = row0 + ty * 4 + r;
#pragma unroll
        for (int c = 0; c < 4; c++) {
            int col = col0 + tx * 4 + c;
            float val = acc[r][c] + bias[col];
            if (mode < 3) {
                int b = row >> 9, s = row & 511;
                int h = col >> 6, dk = col & 63;
                outp[(((size_t)(b * Hn + h) * Sn) + s) * DKn + dk] = val;
            } else {
                outp[(size_t)row * Dn + col] = val;
            }
        }
    }
}

// ---------------------------------------------------------------------------
// scores[b,h,i,j] = (Q[b,h,i,:] . K[b,h,j,:]) / 8   -> written to attn buffer
// ---------------------------------------------------------------------------
__global__ __launch_bounds__(256) void scores_kernel(float* __restrict__ attn)
{
    __shared__ __align__(16) float Qs[64][68];
    __shared__ __align__(16) float Ks[64][68];
    int bh = blockIdx.z;
    const float* Qp = g_q + (size_t)bh * Sn * DKn;
    const float* Kp = g_k + (size_t)bh * Sn * DKn;
    int i0 = blockIdx.y * 64, j0 = blockIdx.x * 64;
    int tid = threadIdx.x, tx = tid & 15, ty = tid >> 4;
#pragma unroll
    for (int l = 0; l < 16; l++) {
        int lin = tid + l * 256;
        int r = lin >> 6, c = lin & 63;
        Qs[c][r] = Qp[(size_t)(i0 + r) * DKn + c];
        Ks[c][r] = Kp[(size_t)(j0 + r) * DKn + c];
    }
    __syncthreads();
    float acc[4][4] = {};
#pragma unroll
    for (int kk = 0; kk < 64; kk++) {
        float4 a = *(const float4*)&Qs[kk][ty * 4];
        float4 w = *(const float4*)&Ks[kk][tx * 4];
        float av[4] = {a.x, a.y, a.z, a.w};
        float wv[4] = {w.x, w.y, w.z, w.w};
#pragma unroll
        for (int r = 0; r < 4; r++)
#pragma unroll
            for (int c = 0; c < 4; c++)
                acc[r][c] += av[r] * wv[c];
    }
    float* dst = attn + ((size_t)bh * Sn + i0) * Sn + j0;
#pragma unroll
    for (int r = 0; r < 4; r++)
#pragma unroll
        for (int c = 0; c < 4; c++)
            dst[(size_t)(ty * 4 + r) * Sn + tx * 4 + c] = acc[r][c] * 0.125f;
}

// ---------------------------------------------------------------------------
// bias[b,h,i,j] += sum_d Q[b,h,i,d] * tm[clip(rp[b,i,j,d],-16,16)+16]
// tm = rel_table.mean(-1). One block per (b,i); idx tile shared across heads.
// ---------------------------------------------------------------------------
__global__ __launch_bounds__(256) void bias_kernel(const int* __restrict__ rp,
                                                   const float* __restrict__ rel_table,
                                                   float* __restrict__ attn)
{
    __shared__ __align__(16) float qs[8][68];
    __shared__ __align__(16) float vbuf[64][68];
    __shared__ float tms[NTAB];
    int i = blockIdx.x;
    int b = blockIdx.y;
    int tid = threadIdx.x;

    if (tid < NTAB) {
        float s = 0.f;
#pragma unroll
        for (int e = 0; e < DKn; e++) s += rel_table[tid * DKn + e];
        tms[tid] = s * (1.0f / DKn);
    }
    for (int l = tid; l < Hn * DKn; l += 256) {
        int h = l >> 6, d = l & 63;
        qs[h][d] = g_q[(((size_t)b * Hn + h) * Sn + i) * DKn + d];
    }
    __syncthreads();

    int jj = tid >> 2, hg = tid & 3;
    int h0 = hg * 2;
    const int4* src = (const int4*)(rp + (((size_t)b * Sn + i) * Sn) * DKn);

    for (int jt = 0; jt < 8; jt++) {
#pragma unroll
        for (int l = 0; l < 4; l++) {
            int q4 = tid + l * 256;                 // int4 index in the 64x64 tile
            int4 v = src[(size_t)jt * 1024 + q4];
            int e = q4 * 4;
            int j = e >> 6, d = e & 63;
            float4 f;
            f.x = tms[min(max(v.x, -16), 16) + 16];
            f.y = tms[min(max(v.y, -16), 16) + 16];
            f.z = tms[min(max(v.z, -16), 16) + 16];
            f.w = tms[min(max(v.w, -16), 16) + 16];
            *(float4*)&vbuf[j][d] = f;
        }
        __syncthreads();
        float acc0 = 0.f, acc1 = 0.f;
#pragma unroll
        for (int dq = 0; dq < 16; dq++) {
            float4 v4 = *(const float4*)&vbuf[jj][dq * 4];
            float4 qa = *(const float4*)&qs[h0][dq * 4];
            float4 qb = *(const float4*)&qs[h0 + 1][dq * 4];
            acc0 += v4.x * qa.x + v4.y * qa.y + v4.z * qa.z + v4.w * qa.w;
            acc1 += v4.x * qb.x + v4.y * qb.y + v4.z * qb.z + v4.w * qb.w;
        }
        size_t base = ((((size_t)b * Hn + h0) * Sn + i) * Sn) + jt * 64 + jj;
        attn[base] += acc0;
        attn[base + (size_t)Sn * Sn] += acc1;
        __syncthreads();
    }
}

// ---------------------------------------------------------------------------
// Row softmax over j (with mask applied BEFORE softmax, matching reference order)
// ---------------------------------------------------------------------------
__global__ __launch_bounds__(128) void softmax_kernel(float* __restrict__ attn,
                                                      const int* __restrict__ mask)
{
    int bhi = blockIdx.x;
    int b = bhi / (Hn * Sn);
    float* row = attn + (size_t)bhi * Sn;
    int tid = threadIdx.x;
    float v[4];
    float mx = -3.0e38f;
#pragma unroll
    for (int k = 0; k < 4; k++) {
        int j = tid + k * 128;
        float x = row[j];
        if (mask[b * Sn + j] == 0) x = -1e9f;
        v[k] = x;
        mx = fmaxf(mx, x);
    }
    __shared__ float red[4];
#pragma unroll
    for (int off = 16; off; off >>= 1) mx = fmaxf(mx, __shfl_xor_sync(0xffffffffu, mx, off));
    if ((tid & 31) == 0) red[tid >> 5] = mx;
    __syncthreads();
    mx = fmaxf(fmaxf(red[0], red[1]), fmaxf(red[2], red[3]));
    __syncthreads();
    float s = 0.f;
#pragma unroll
    for (int k = 0; k < 4; k++) { v[k] = expf(v[k] - mx); s += v[k]; }
#pragma unroll
    for (int off = 16; off; off >>= 1) s += __shfl_xor_sync(0xffffffffu, s, off);
    if ((tid & 31) == 0) red[tid >> 5] = s;
    __syncthreads();
    s = red[0] + red[1] + red[2] + red[3];
    float inv = 1.0f / s;
#pragma unroll
    for (int k = 0; k < 4; k++) row[tid + k * 128] = v[k] * inv;
}

// ---------------------------------------------------------------------------
// ctx[b,i,h*64+d] = sum_j attn[b,h,i,j] * V[b,h,j,d]
// ---------------------------------------------------------------------------
__global__ __launch_bounds__(256) void av_kernel(const float* __restrict__ attn)
{
    __shared__ __align__(16) float As[32][68];
    __shared__ __align__(16) float Vs[32][68];
    int bh = blockIdx.y;
    int b = bh >> 3, h = bh & 7;
    int i0 = blockIdx.x * 64;
    const float* Ap = attn + (size_t)bh * Sn * Sn;
    const float* Vp = g_v + (size_t)bh * Sn * DKn;
    int tid = threadIdx.x, tx = tid & 15, ty = tid >> 4;
    float acc[4][4] = {};
    for (int j0 = 0; j0 < Sn; j0 += 32) {
#pragma unroll
        for (int l = 0; l < 8; l++) {
            int lin = tid + l * 256;
            {
                int r = lin >> 5, kk = lin & 31;
                As[kk][r] = Ap[(size_t)(i0 + r) * Sn + j0 + kk];
            }
            {
                int kk = lin >> 6, c = lin & 63;
                Vs[kk][c] = Vp[(size_t)(j0 + kk) * DKn + c];
            }
        }
        __syncthreads();
#pragma unroll
        for (int kk = 0; kk < 32; kk++) {
            float4 a = *(const float4*)&As[kk][ty * 4];
            float4 w = *(const float4*)&Vs[kk][tx * 4];
            float av[4] = {a.x, a.y, a.z, a.w};
            float wv[4] = {w.x, w.y, w.z, w.w};
#pragma unroll
            for (int r = 0; r < 4; r++)
#pragma unroll
                for (int c = 0; c < 4; c++)
                    acc[r][c] += av[r] * wv[c];
        }
        __syncthreads();
    }
#pragma unroll
    for (int r = 0; r < 4; r++)
#pragma unroll
        for (int c = 0; c < 4; c++)
            g_ctx[((size_t)b * Sn + i0 + ty * 4 + r) * Dn + h * DKn + tx * 4 + c] = acc[r][c];
}

// ---------------------------------------------------------------------------
// y = LayerNorm(g_out + query) * gamma + beta    (one block per row)
// ---------------------------------------------------------------------------
__global__ __launch_bounds__(256) void ln_kernel(const float* __restrict__ query,
                                                 const float* __restrict__ gamma,
                                                 const float* __restrict__ beta,
                                                 float* __restrict__ y)
{
    int row = blockIdx.x;
    int tid = threadIdx.x;
    size_t base = (size_t)row * Dn;
    float x0 = g_out[base + tid] + query[base + tid];
    float x1 = g_out[base + tid + 256] + query[base + tid + 256];
    float s = x0 + x1, sq = x0 * x0 + x1 * x1;
    __shared__ float r1[8], r2[8];
#pragma unroll
    for (int off = 16; off; off >>= 1) {
        s += __shfl_xor_sync(0xffffffffu, s, off);
        sq += __shfl_xor_sync(0xffffffffu, sq, off);
    }
    if ((tid & 31) == 0) { r1[tid >> 5] = s; r2[tid >> 5] = sq; }
    __syncthreads();
    s = 0.f; sq = 0.f;
#pragma unroll
    for (int w = 0; w < 8; w++) { s += r1[w]; sq += r2[w]; }
    float mean = s * (1.0f / Dn);
    float var = sq * (1.0f / Dn) - mean * mean;
    float rstd = rsqrtf(var + 1e-5f);
    y[base + tid]       = (x0 - mean) * rstd * gamma[tid] + beta[tid];
    y[base + tid + 256] = (x1 - mean) * rstd * gamma[tid + 256] + beta[tid + 256];
}

// ---------------------------------------------------------------------------
extern "C" void kernel_launch(void* const* d_in, const int* in_sizes, int n_in,
                              void* d_out, int out_size)
{
    (void)in_sizes; (void)n_in; (void)out_size;
    const float* query = (const float*)d_in[0];
    const float* key   = (const float*)d_in[1];
    const float* value = (const float*)d_in[2];
    const float* Wq = (const float*)d_in[3];
    const float* bq = (const float*)d_in[4];
    const float* Wk = (const float*)d_in[5];
    const float* bk = (const float*)d_in[6];
    const float* Wv = (const float*)d_in[7];
    const float* bv = (const float*)d_in[8];
    const float* Wo = (const float*)d_in[9];
    const float* bo = (const float*)d_in[10];
    const float* rel_table = (const float*)d_in[11];
    const float* gamma = (const float*)d_in[12];
    const float* beta  = (const float*)d_in[13];
    const int* mask = (const int*)d_in[14];
    const int* rp   = (const int*)d_in[15];

    float* y = (float*)d_out;                        // [B,S,D]
    float* attn = y + (size_t)Bn * Sn * Dn;          // [B,H,S,S]

    dim3 g1(Dn / 64, (Bn * Sn) / 64);
    gemm_kernel<<<g1, 256>>>(query, Wq, bq, 0);
    gemm_kernel<<<g1, 256>>>(key,   Wk, bk, 1);
    gemm_kernel<<<g1, 256>>>(value, Wv, bv, 2);
    scores_kernel<<<dim3(Sn / 64, Sn / 64, Bn * Hn), 256>>>(attn);
    bias_kernel<<<dim3(Sn, Bn), 256>>>(rp, rel_table, attn);
    softmax_kernel<<<Bn * Hn * Sn, 128>>>(attn, mask);
    av_kernel<<<dim3(Sn / 64, Bn * Hn), 256>>>(attn);
    gemm_kernel<<<g1, 256>>>(nullptr, Wo, bo, 3);    // out-proj from g_ctx
    ln_kernel<<<Bn * Sn, 256>>>(query, gamma, beta, y);
}

// round 5
// speedup vs baseline: 2.9704x; 2.9704x over previous
#include <cuda_runtime.h>
#include <math.h>
#include <stdint.h>

#define Bn 4
#define Sn 512
#define Dn 512
#define Hn 8
#define DKn 64
#define NTAB 33

// Scratch (no allocations allowed -> __device__ globals)
__device__ float g_q[Bn*Hn*Sn*DKn];
__device__ float g_k[Bn*Hn*Sn*DKn];
__device__ float g_vT[Bn*Hn*DKn*Sn];   // V transposed: [b,h,dk,s]
__device__ float g_ctx[(size_t)Bn*Sn*Dn];
__device__ float g_out[(size_t)Bn*Sn*Dn];

__device__ __forceinline__ uint32_t to_tf32(float f) {
    uint32_t u;
    asm("cvt.rna.tf32.f32 %0, %1;" : "=r"(u) : "f"(f));
    return u;
}

__device__ __forceinline__ void mma_tf32(float* c, const uint32_t* a, const uint32_t* b) {
    asm volatile(
        "mma.sync.aligned.m16n8k8.row.col.f32.tf32.tf32.f32 "
        "{%0,%1,%2,%3}, {%4,%5,%6,%7}, {%8,%9}, {%0,%1,%2,%3};"
        : "+f"(c[0]), "+f"(c[1]), "+f"(c[2]), "+f"(c[3])
        : "r"(a[0]), "r"(a[1]), "r"(a[2]), "r"(a[3]), "r"(b[0]), "r"(b[1]));
}

// ===========================================================================
// Unified tensor-core tf32 GEMM: D[m,n] = sum_k A[m,k]*B[n,k]
//  mode 0/1/2 (z picks Q/K/V): proj, A=[2048,512] input, B=W; scatter epilogue
//  mode 3: out-proj  A=g_ctx, B=Wo -> g_out
//  mode 4: scores    A=Q_head[i,dk], B=K_head[j,dk] -> attn[b,h,i,j]*0.125
//  mode 5: attn*V    A=attn[i,j],    B=g_vT[d,j]    -> g_ctx
// Block tile 128x64, 256 threads (8 warps: 4 along M x 2 along N),
// warp tile 32x32 (2 m-frags x 4 n-frags), K in 32-chunks, double-buffered.
// ===========================================================================
#define AW 4608   // 128*36 words per A buffer
#define BW 2304   // 64*36 words per B buffer
#define BUFW 6912

__global__ __launch_bounds__(256) void tc_gemm(
    const float* __restrict__ A0, const float* __restrict__ A1, const float* __restrict__ A2,
    const float* __restrict__ B0, const float* __restrict__ B1, const float* __restrict__ B2,
    const float* __restrict__ bias0, const float* __restrict__ bias1, const float* __restrict__ bias2,
    float* __restrict__ attn, int mode, int kTot)
{
    extern __shared__ uint32_t smem_u[];
    int tid = threadIdx.x;
    int wid = tid >> 5, lane = tid & 31;
    int wm = wid & 3, wn = wid >> 2;
    int g = lane >> 2, t4 = lane & 3;

    int row0 = blockIdx.y * 128;
    int n0   = blockIdx.x * 64;
    int bh   = blockIdx.z;

    const float* Ap; const float* Bp; const float* biasp = nullptr;
    int ldA, ldB, emode;
    if (mode == 0) {
        int w = bh;
        Ap = (w == 0) ? A0 : (w == 1) ? A1 : A2;
        Bp = (w == 0) ? B0 : (w == 1) ? B1 : B2;
        biasp = (w == 0) ? bias0 : (w == 1) ? bias1 : bias2;
        ldA = Dn; ldB = Dn; emode = w;
    } else if (mode == 3) {
        Ap = g_ctx; Bp = B0; biasp = bias0; ldA = Dn; ldB = Dn; emode = 3;
    } else if (mode == 4) {
        Ap = g_q + (size_t)bh * Sn * DKn;   // M = queries (i)
        Bp = g_k + (size_t)bh * Sn * DKn;   // N = keys (j)
        ldA = DKn; ldB = DKn; emode = 4;
    } else {
        Ap = attn + (size_t)bh * Sn * Sn;   // M = queries (i), K = j
        Bp = g_vT + (size_t)bh * DKn * Sn;  // N = d
        ldA = Sn; ldB = Sn; emode = 5;
    }
    Ap += (size_t)row0 * ldA;
    Bp += (size_t)n0 * ldB;

    float acc[2][4][4];
#pragma unroll
    for (int mi = 0; mi < 2; mi++)
#pragma unroll
        for (int ni = 0; ni < 4; ni++)
#pragma unroll
            for (int q = 0; q < 4; q++) acc[mi][ni][q] = 0.f;

    float4 pa[4], pb[2];
    // prefetch chunk 0
    {
        int r = tid >> 3, c4 = tid & 7;   // A: 1024 float4, 4 per thread
#pragma unroll
        for (int l = 0; l < 4; l++)
            pa[l] = *(const float4*)(Ap + (size_t)(r + l * 32) * ldA + c4 * 4);
#pragma unroll
        for (int l = 0; l < 2; l++)
            pb[l] = *(const float4*)(Bp + (size_t)(r + l * 32) * ldB + c4 * 4);
    }
    {
        int r = tid >> 3, c4 = tid & 7;
        uint32_t* As = smem_u;
        uint32_t* Bs = smem_u + AW;
#pragma unroll
        for (int l = 0; l < 4; l++) {
            uint32_t* d = As + (r + l * 32) * 36 + c4 * 4;
            d[0] = to_tf32(pa[l].x); d[1] = to_tf32(pa[l].y);
            d[2] = to_tf32(pa[l].z); d[3] = to_tf32(pa[l].w);
        }
#pragma unroll
        for (int l = 0; l < 2; l++) {
            uint32_t* d = Bs + (r + l * 32) * 36 + c4 * 4;
            d[0] = to_tf32(pb[l].x); d[1] = to_tf32(pb[l].y);
            d[2] = to_tf32(pb[l].z); d[3] = to_tf32(pb[l].w);
        }
    }
    __syncthreads();

    int nk = kTot / 32;
    for (int kc = 0; kc < nk; kc++) {
        // prefetch next chunk (gmem latency hidden behind MMAs)
        if (kc + 1 < nk) {
            int k0 = (kc + 1) * 32;
            int r = tid >> 3, c4 = tid & 7;
#pragma unroll
            for (int l = 0; l < 4; l++)
                pa[l] = *(const float4*)(Ap + (size_t)(r + l * 32) * ldA + k0 + c4 * 4);
#pragma unroll
            for (int l = 0; l < 2; l++)
                pb[l] = *(const float4*)(Bp + (size_t)(r + l * 32) * ldB + k0 + c4 * 4);
        }
        const uint32_t* As = smem_u + (kc & 1) * BUFW;
        const uint32_t* Bs = As + AW;
#pragma unroll
        for (int kk = 0; kk < 4; kk++) {
            int kb = kk * 8 + t4;
            uint32_t a[2][4], b[4][2];
#pragma unroll
            for (int mi = 0; mi < 2; mi++) {
                int r = (wm * 32 + mi * 16 + g) * 36 + kb;
                a[mi][0] = As[r];
                a[mi][1] = As[r + 8 * 36];
                a[mi][2] = As[r + 4];
                a[mi][3] = As[r + 8 * 36 + 4];
            }
#pragma unroll
            for (int ni = 0; ni < 4; ni++) {
                int r = (wn * 32 + ni * 8 + g) * 36 + kb;
                b[ni][0] = Bs[r];
                b[ni][1] = Bs[r + 4];
            }
#pragma unroll
            for (int mi = 0; mi < 2; mi++)
#pragma unroll
                for (int ni = 0; ni < 4; ni++)
                    mma_tf32(acc[mi][ni], a[mi], b[ni]);
        }
        if (kc + 1 < nk) {
            uint32_t* Aw = smem_u + ((kc + 1) & 1) * BUFW;
            uint32_t* Bw = Aw + AW;
            int r = tid >> 3, c4 = tid & 7;
#pragma unroll
            for (int l = 0; l < 4; l++) {
                uint32_t* d = Aw + (r + l * 32) * 36 + c4 * 4;
                d[0] = to_tf32(pa[l].x); d[1] = to_tf32(pa[l].y);
                d[2] = to_tf32(pa[l].z); d[3] = to_tf32(pa[l].w);
            }
#pragma unroll
            for (int l = 0; l < 2; l++) {
                uint32_t* d = Bw + (r + l * 32) * 36 + c4 * 4;
                d[0] = to_tf32(pb[l].x); d[1] = to_tf32(pb[l].y);
                d[2] = to_tf32(pb[l].z); d[3] = to_tf32(pb[l].w);
            }
            __syncthreads();
        }
    }

    // Epilogue: c0/c1 at (row, col|col+1), c2/c3 at (row+8, same cols)
#pragma unroll
    for (int mi = 0; mi < 2; mi++) {
        int row = row0 + wm * 32 + mi * 16 + g;
#pragma unroll
        for (int ni = 0; ni < 4; ni++) {
            int col = n0 + wn * 32 + ni * 8 + 2 * t4;
            float v0 = acc[mi][ni][0], v1 = acc[mi][ni][1];
            float v2 = acc[mi][ni][2], v3 = acc[mi][ni][3];
            if (emode <= 3) {
                float b0v = biasp[col], b1v = biasp[col + 1];
                v0 += b0v; v1 += b1v; v2 += b0v; v3 += b1v;
            }
            if (emode <= 2) {
                int b = row >> 9, s = row & 511;
                int h = col >> 6, dk = col & 63;
                if (emode == 0) {
                    float* p = g_q + (((size_t)(b * Hn + h)) * Sn + s) * DKn + dk;
                    *(float2*)p = make_float2(v0, v1);
                    *(float2*)(p + 8 * DKn) = make_float2(v2, v3);
                } else if (emode == 1) {
                    float* p = g_k + (((size_t)(b * Hn + h)) * Sn + s) * DKn + dk;
                    *(float2*)p = make_float2(v0, v1);
                    *(float2*)(p + 8 * DKn) = make_float2(v2, v3);
                } else {
                    float* p = g_vT + (((size_t)(b * Hn + h)) * DKn + dk) * Sn + s;
                    p[0] = v0; p[Sn] = v1; p[8] = v2; p[Sn + 8] = v3;
                }
            } else if (emode == 3) {
                float* p = g_out + (size_t)row * Dn + col;
                *(float2*)p = make_float2(v0, v1);
                *(float2*)(p + 8 * Dn) = make_float2(v2, v3);
            } else if (emode == 4) {
                float* p = attn + ((size_t)bh * Sn + row) * Sn + col;
                *(float2*)p = make_float2(v0 * 0.125f, v1 * 0.125f);
                *(float2*)(p + 8 * Sn) = make_float2(v2 * 0.125f, v3 * 0.125f);
            } else {
                int b = bh >> 3, h = bh & 7;
                float* p = g_ctx + ((size_t)b * Sn + row) * Dn + h * DKn + col;
                *(float2*)p = make_float2(v0, v1);
                *(float2*)(p + 8 * Dn) = make_float2(v2, v3);
            }
        }
    }
}

// ---------------------------------------------------------------------------
// bias[b,h,i,j] += sum_d Q[b,h,i,d] * tm[clip(rp[b,i,j,d],-16,16)+16]
// ---------------------------------------------------------------------------
__global__ __launch_bounds__(256) void bias_kernel(const int* __restrict__ rp,
                                                   const float* __restrict__ rel_table,
                                                   float* __restrict__ attn)
{
    __shared__ __align__(16) float qs[8][68];
    __shared__ __align__(16) float vbuf[64][68];
    __shared__ float tms[NTAB];
    int i = blockIdx.x;
    int b = blockIdx.y;
    int tid = threadIdx.x;

    if (tid < NTAB) {
        float s = 0.f;
#pragma unroll
        for (int e = 0; e < DKn; e++) s += rel_table[tid * DKn + e];
        tms[tid] = s * (1.0f / DKn);
    }
    for (int l = tid; l < Hn * DKn; l += 256) {
        int h = l >> 6, d = l & 63;
        qs[h][d] = g_q[(((size_t)b * Hn + h) * Sn + i) * DKn + d];
    }
    __syncthreads();

    int jj = tid >> 2, hg = tid & 3;
    int h0 = hg * 2;
    const int4* src = (const int4*)(rp + (((size_t)b * Sn + i) * Sn) * DKn);

    for (int jt = 0; jt < 8; jt++) {
#pragma unroll
        for (int l = 0; l < 4; l++) {
            int q4 = tid + l * 256;
            int4 v = src[(size_t)jt * 1024 + q4];
            int e = q4 * 4;
            int j = e >> 6, d = e & 63;
            float4 f;
            f.x = tms[min(max(v.x, -16), 16) + 16];
            f.y = tms[min(max(v.y, -16), 16) + 16];
            f.z = tms[min(max(v.z, -16), 16) + 16];
            f.w = tms[min(max(v.w, -16), 16) + 16];
            *(float4*)&vbuf[j][d] = f;
        }
        __syncthreads();
        float acc0 = 0.f, acc1 = 0.f;
#pragma unroll
        for (int dq = 0; dq < 16; dq++) {
            float4 v4 = *(const float4*)&vbuf[jj][dq * 4];
            float4 qa = *(const float4*)&qs[h0][dq * 4];
            float4 qb = *(const float4*)&qs[h0 + 1][dq * 4];
            acc0 += v4.x * qa.x + v4.y * qa.y + v4.z * qa.z + v4.w * qa.w;
            acc1 += v4.x * qb.x + v4.y * qb.y + v4.z * qb.z + v4.w * qb.w;
        }
        size_t base = ((((size_t)b * Hn + h0) * Sn + i) * Sn) + jt * 64 + jj;
        attn[base] += acc0;
        attn[base + (size_t)Sn * Sn] += acc1;
        __syncthreads();
    }
}

// ---------------------------------------------------------------------------
__global__ __launch_bounds__(128) void softmax_kernel(float* __restrict__ attn,
                                                      const int* __restrict__ mask)
{
    int bhi = blockIdx.x;
    int b = bhi / (Hn * Sn);
    float* row = attn + (size_t)bhi * Sn;
    int tid = threadIdx.x;
    float v[4];
    float mx = -3.0e38f;
#pragma unroll
    for (int k = 0; k < 4; k++) {
        int j = tid + k * 128;
        float x = row[j];
        if (mask[b * Sn + j] == 0) x = -1e9f;
        v[k] = x;
        mx = fmaxf(mx, x);
    }
    __shared__ float red[4];
#pragma unroll
    for (int off = 16; off; off >>= 1) mx = fmaxf(mx, __shfl_xor_sync(0xffffffffu, mx, off));
    if ((tid & 31) == 0) red[tid >> 5] = mx;
    __syncthreads();
    mx = fmaxf(fmaxf(red[0], red[1]), fmaxf(red[2], red[3]));
    __syncthreads();
    float s = 0.f;
#pragma unroll
    for (int k = 0; k < 4; k++) { v[k] = expf(v[k] - mx); s += v[k]; }
#pragma unroll
    for (int off = 16; off; off >>= 1) s += __shfl_xor_sync(0xffffffffu, s, off);
    if ((tid & 31) == 0) red[tid >> 5] = s;
    __syncthreads();
    s = red[0] + red[1] + red[2] + red[3];
    float inv = 1.0f / s;
#pragma unroll
    for (int k = 0; k < 4; k++) row[tid + k * 128] = v[k] * inv;
}

// ---------------------------------------------------------------------------
__global__ __launch_bounds__(256) void ln_kernel(const float* __restrict__ query,
                                                 const float* __restrict__ gamma,
                                                 const float* __restrict__ beta,
                                                 float* __restrict__ y)
{
    int row = blockIdx.x;
    int tid = threadIdx.x;
    size_t base = (size_t)row * Dn;
    float x0 = g_out[base + tid] + query[base + tid];
    float x1 = g_out[base + tid + 256] + query[base + tid + 256];
    float s = x0 + x1, sq = x0 * x0 + x1 * x1;
    __shared__ float r1[8], r2[8];
#pragma unroll
    for (int off = 16; off; off >>= 1) {
        s += __shfl_xor_sync(0xffffffffu, s, off);
        sq += __shfl_xor_sync(0xffffffffu, sq, off);
    }
    if ((tid & 31) == 0) { r1[tid >> 5] = s; r2[tid >> 5] = sq; }
    __syncthreads();
    s = 0.f; sq = 0.f;
#pragma unroll
    for (int w = 0; w < 8; w++) { s += r1[w]; sq += r2[w]; }
    float mean = s * (1.0f / Dn);
    float var = sq * (1.0f / Dn) - mean * mean;
    float rstd = rsqrtf(var + 1e-5f);
    y[base + tid]       = (x0 - mean) * rstd * gamma[tid] + beta[tid];
    y[base + tid + 256] = (x1 - mean) * rstd * gamma[tid + 256] + beta[tid + 256];
}

// ---------------------------------------------------------------------------
extern "C" void kernel_launch(void* const* d_in, const int* in_sizes, int n_in,
                              void* d_out, int out_size)
{
    (void)in_sizes; (void)n_in; (void)out_size;
    const float* query = (const float*)d_in[0];
    const float* key   = (const float*)d_in[1];
    const float* value = (const float*)d_in[2];
    const float* Wq = (const float*)d_in[3];
    const float* bq = (const float*)d_in[4];
    const float* Wk = (const float*)d_in[5];
    const float* bk = (const float*)d_in[6];
    const float* Wv = (const float*)d_in[7];
    const float* bv = (const float*)d_in[8];
    const float* Wo = (const float*)d_in[9];
    const float* bo = (const float*)d_in[10];
    const float* rel_table = (const float*)d_in[11];
    const float* gamma = (const float*)d_in[12];
    const float* beta  = (const float*)d_in[13];
    const int* mask = (const int*)d_in[14];
    const int* rp   = (const int*)d_in[15];

    float* y = (float*)d_out;                        // [B,S,D]
    float* attn = y + (size_t)Bn * Sn * Dn;          // [B,H,S,S]

    const int SMB = 2 * BUFW * 4;                    // 55296 bytes
    cudaFuncSetAttribute(tc_gemm, cudaFuncAttributeMaxDynamicSharedMemorySize, SMB);

    // fused QKV projections
    tc_gemm<<<dim3(8, 16, 3), 256, SMB>>>(query, key, value, Wq, Wk, Wv,
                                          bq, bk, bv, nullptr, 0, 512);
    // scores
    tc_gemm<<<dim3(8, 4, 32), 256, SMB>>>(nullptr, nullptr, nullptr, nullptr, nullptr, nullptr,
                                          nullptr, nullptr, nullptr, attn, 4, 64);
    bias_kernel<<<dim3(Sn, Bn), 256>>>(rp, rel_table, attn);
    softmax_kernel<<<Bn * Hn * Sn, 128>>>(attn, mask);
    // attn @ V
    tc_gemm<<<dim3(1, 4, 32), 256, SMB>>>(nullptr, nullptr, nullptr, nullptr, nullptr, nullptr,
                                          nullptr, nullptr, nullptr, attn, 5, 512);
    // out projection
    tc_gemm<<<dim3(8, 16, 1), 256, SMB>>>(nullptr, nullptr, nullptr, Wo, nullptr, nullptr,
                                          bo, nullptr, nullptr, nullptr, 3, 512);
    ln_kernel<<<Bn * Sn, 256>>>(query, gamma, beta, y);
}

// round 6
// speedup vs baseline: 3.1235x; 1.0516x over previous
#include <cuda_runtime.h>
#include <math.h>
#include <stdint.h>

#define Bn 4
#define Sn 512
#define Dn 512
#define Hn 8
#define DKn 64
#define NTAB 33

// Scratch (no allocations allowed -> __device__ globals)
__device__ float g_q[Bn*Hn*Sn*DKn];
__device__ float g_k[Bn*Hn*Sn*DKn];
__device__ float g_vT[Bn*Hn*DKn*Sn];   // V transposed: [b,h,dk,s]
__device__ float g_ctx[(size_t)Bn*Sn*Dn];
__device__ float g_out[(size_t)Bn*Sn*Dn];

__device__ __forceinline__ uint32_t to_tf32(float f) {
    uint32_t u;
    asm("cvt.rna.tf32.f32 %0, %1;" : "=r"(u) : "f"(f));
    return u;
}

__device__ __forceinline__ void mma_tf32(float* c, const uint32_t* a, const uint32_t* b) {
    asm volatile(
        "mma.sync.aligned.m16n8k8.row.col.f32.tf32.tf32.f32 "
        "{%0,%1,%2,%3}, {%4,%5,%6,%7}, {%8,%9}, {%0,%1,%2,%3};"
        : "+f"(c[0]), "+f"(c[1]), "+f"(c[2]), "+f"(c[3])
        : "r"(a[0]), "r"(a[1]), "r"(a[2]), "r"(a[3]), "r"(b[0]), "r"(b[1]));
}

// ===========================================================================
// Unified tensor-core tf32 GEMM (same as R5): D[m,n] = sum_k A[m,k]*B[n,k]
// ===========================================================================
#define AW 4608   // 128*36 words per A buffer
#define BW 2304   // 64*36 words per B buffer
#define BUFW 6912

__global__ __launch_bounds__(256) void tc_gemm(
    const float* __restrict__ A0, const float* __restrict__ A1, const float* __restrict__ A2,
    const float* __restrict__ B0, const float* __restrict__ B1, const float* __restrict__ B2,
    const float* __restrict__ bias0, const float* __restrict__ bias1, const float* __restrict__ bias2,
    float* __restrict__ attn, int mode, int kTot)
{
    extern __shared__ uint32_t smem_u[];
    int tid = threadIdx.x;
    int wid = tid >> 5, lane = tid & 31;
    int wm = wid & 3, wn = wid >> 2;
    int g = lane >> 2, t4 = lane & 3;

    int row0 = blockIdx.y * 128;
    int n0   = blockIdx.x * 64;
    int bh   = blockIdx.z;

    const float* Ap; const float* Bp; const float* biasp = nullptr;
    int ldA, ldB, emode;
    if (mode == 0) {
        int w = bh;
        Ap = (w == 0) ? A0 : (w == 1) ? A1 : A2;
        Bp = (w == 0) ? B0 : (w == 1) ? B1 : B2;
        biasp = (w == 0) ? bias0 : (w == 1) ? bias1 : bias2;
        ldA = Dn; ldB = Dn; emode = w;
    } else if (mode == 3) {
        Ap = g_ctx; Bp = B0; biasp = bias0; ldA = Dn; ldB = Dn; emode = 3;
    } else if (mode == 4) {
        Ap = g_q + (size_t)bh * Sn * DKn;   // M = queries (i)
        Bp = g_k + (size_t)bh * Sn * DKn;   // N = keys (j)
        ldA = DKn; ldB = DKn; emode = 4;
    } else {
        Ap = attn + (size_t)bh * Sn * Sn;   // M = queries (i), K = j
        Bp = g_vT + (size_t)bh * DKn * Sn;  // N = d
        ldA = Sn; ldB = Sn; emode = 5;
    }
    Ap += (size_t)row0 * ldA;
    Bp += (size_t)n0 * ldB;

    float acc[2][4][4];
#pragma unroll
    for (int mi = 0; mi < 2; mi++)
#pragma unroll
        for (int ni = 0; ni < 4; ni++)
#pragma unroll
            for (int q = 0; q < 4; q++) acc[mi][ni][q] = 0.f;

    float4 pa[4], pb[2];
    {
        int r = tid >> 3, c4 = tid & 7;
#pragma unroll
        for (int l = 0; l < 4; l++)
            pa[l] = *(const float4*)(Ap + (size_t)(r + l * 32) * ldA + c4 * 4);
#pragma unroll
        for (int l = 0; l < 2; l++)
            pb[l] = *(const float4*)(Bp + (size_t)(r + l * 32) * ldB + c4 * 4);
    }
    {
        int r = tid >> 3, c4 = tid & 7;
        uint32_t* As = smem_u;
        uint32_t* Bs = smem_u + AW;
#pragma unroll
        for (int l = 0; l < 4; l++) {
            uint32_t* d = As + (r + l * 32) * 36 + c4 * 4;
            d[0] = to_tf32(pa[l].x); d[1] = to_tf32(pa[l].y);
            d[2] = to_tf32(pa[l].z); d[3] = to_tf32(pa[l].w);
        }
#pragma unroll
        for (int l = 0; l < 2; l++) {
            uint32_t* d = Bs + (r + l * 32) * 36 + c4 * 4;
            d[0] = to_tf32(pb[l].x); d[1] = to_tf32(pb[l].y);
            d[2] = to_tf32(pb[l].z); d[3] = to_tf32(pb[l].w);
        }
    }
    __syncthreads();

    int nk = kTot / 32;
    for (int kc = 0; kc < nk; kc++) {
        if (kc + 1 < nk) {
            int k0 = (kc + 1) * 32;
            int r = tid >> 3, c4 = tid & 7;
#pragma unroll
            for (int l = 0; l < 4; l++)
                pa[l] = *(const float4*)(Ap + (size_t)(r + l * 32) * ldA + k0 + c4 * 4);
#pragma unroll
            for (int l = 0; l < 2; l++)
                pb[l] = *(const float4*)(Bp + (size_t)(r + l * 32) * ldB + k0 + c4 * 4);
        }
        const uint32_t* As = smem_u + (kc & 1) * BUFW;
        const uint32_t* Bs = As + AW;
#pragma unroll
        for (int kk = 0; kk < 4; kk++) {
            int kb = kk * 8 + t4;
            uint32_t a[2][4], b[4][2];
#pragma unroll
            for (int mi = 0; mi < 2; mi++) {
                int r = (wm * 32 + mi * 16 + g) * 36 + kb;
                a[mi][0] = As[r];
                a[mi][1] = As[r + 8 * 36];
                a[mi][2] = As[r + 4];
                a[mi][3] = As[r + 8 * 36 + 4];
            }
#pragma unroll
            for (int ni = 0; ni < 4; ni++) {
                int r = (wn * 32 + ni * 8 + g) * 36 + kb;
                b[ni][0] = Bs[r];
                b[ni][1] = Bs[r + 4];
            }
#pragma unroll
            for (int mi = 0; mi < 2; mi++)
#pragma unroll
                for (int ni = 0; ni < 4; ni++)
                    mma_tf32(acc[mi][ni], a[mi], b[ni]);
        }
        if (kc + 1 < nk) {
            uint32_t* Aw = smem_u + ((kc + 1) & 1) * BUFW;
            uint32_t* Bw = Aw + AW;
            int r = tid >> 3, c4 = tid & 7;
#pragma unroll
            for (int l = 0; l < 4; l++) {
                uint32_t* d = Aw + (r + l * 32) * 36 + c4 * 4;
                d[0] = to_tf32(pa[l].x); d[1] = to_tf32(pa[l].y);
                d[2] = to_tf32(pa[l].z); d[3] = to_tf32(pa[l].w);
            }
#pragma unroll
            for (int l = 0; l < 2; l++) {
                uint32_t* d = Bw + (r + l * 32) * 36 + c4 * 4;
                d[0] = to_tf32(pb[l].x); d[1] = to_tf32(pb[l].y);
                d[2] = to_tf32(pb[l].z); d[3] = to_tf32(pb[l].w);
            }
            __syncthreads();
        }
    }

#pragma unroll
    for (int mi = 0; mi < 2; mi++) {
        int row = row0 + wm * 32 + mi * 16 + g;
#pragma unroll
        for (int ni = 0; ni < 4; ni++) {
            int col = n0 + wn * 32 + ni * 8 + 2 * t4;
            float v0 = acc[mi][ni][0], v1 = acc[mi][ni][1];
            float v2 = acc[mi][ni][2], v3 = acc[mi][ni][3];
            if (emode <= 3) {
                float b0v = biasp[col], b1v = biasp[col + 1];
                v0 += b0v; v1 += b1v; v2 += b0v; v3 += b1v;
            }
            if (emode <= 2) {
                int b = row >> 9, s = row & 511;
                int h = col >> 6, dk = col & 63;
                if (emode == 0) {
                    float* p = g_q + (((size_t)(b * Hn + h)) * Sn + s) * DKn + dk;
                    *(float2*)p = make_float2(v0, v1);
                    *(float2*)(p + 8 * DKn) = make_float2(v2, v3);
                } else if (emode == 1) {
                    float* p = g_k + (((size_t)(b * Hn + h)) * Sn + s) * DKn + dk;
                    *(float2*)p = make_float2(v0, v1);
                    *(float2*)(p + 8 * DKn) = make_float2(v2, v3);
                } else {
                    float* p = g_vT + (((size_t)(b * Hn + h)) * DKn + dk) * Sn + s;
                    p[0] = v0; p[Sn] = v1; p[8] = v2; p[Sn + 8] = v3;
                }
            } else if (emode == 3) {
                float* p = g_out + (size_t)row * Dn + col;
                *(float2*)p = make_float2(v0, v1);
                *(float2*)(p + 8 * Dn) = make_float2(v2, v3);
            } else if (emode == 4) {
                float* p = attn + ((size_t)bh * Sn + row) * Sn + col;
                *(float2*)p = make_float2(v0 * 0.125f, v1 * 0.125f);
                *(float2*)(p + 8 * Sn) = make_float2(v2 * 0.125f, v3 * 0.125f);
            } else {
                int b = bh >> 3, h = bh & 7;
                float* p = g_ctx + ((size_t)b * Sn + row) * Dn + h * DKn + col;
                *(float2*)p = make_float2(v0, v1);
                *(float2*)(p + 8 * Dn) = make_float2(v2, v3);
            }
        }
    }
}

// ===========================================================================
// Fused relative-position bias + mask + softmax.
// One block per (b,i). Computes for all 8 heads:
//   s[h][j] = attn[b,h,i,j] + sum_d Q[b,h,i,d]*tm[clip(rp[b,i,j,d])]
//   attn[b,h,i,:] = softmax(mask ? s : -1e9)
// Idx tile double-buffered in registers (4x LDG.128 in flight during compute).
// ===========================================================================
__global__ __launch_bounds__(256) void bias_softmax_kernel(
    const int* __restrict__ rp, const float* __restrict__ rel_table,
    const int* __restrict__ mask, float* __restrict__ attn)
{
    __shared__ __align__(16) float qs[8][68];
    __shared__ __align__(16) float vbuf[64][68];
    __shared__ __align__(16) float s_row[8][Sn];
    __shared__ float tms[NTAB + 3];
    __shared__ int mask_s[Sn];

    int i = blockIdx.x;
    int b = blockIdx.y;
    int tid = threadIdx.x;

    if (tid < NTAB) {
        float s = 0.f;
#pragma unroll
        for (int e = 0; e < DKn; e++) s += rel_table[tid * DKn + e];
        tms[tid] = s * (1.0f / DKn);
    }
    for (int l = tid; l < Hn * DKn; l += 256) {
        int h = l >> 6, d = l & 63;
        qs[h][d] = g_q[(((size_t)b * Hn + h) * Sn + i) * DKn + d];
    }
    {
        int m0 = mask[b * Sn + tid];
        int m1 = mask[b * Sn + tid + 256];
        mask_s[tid] = m0;
        mask_s[tid + 256] = m1;
    }

    int jj = tid >> 2, hg = tid & 3;
    int h0 = hg * 2;
    const int4* src = (const int4*)(rp + (((size_t)b * Sn + i) * Sn) * DKn);

    int4 pre[4];
#pragma unroll
    for (int l = 0; l < 4; l++) pre[l] = src[tid + l * 256];
    __syncthreads();

    for (int jt = 0; jt < 8; jt++) {
#pragma unroll
        for (int l = 0; l < 4; l++) {
            int q4 = tid + l * 256;
            int4 v = pre[l];
            int e = q4 * 4;
            int j = e >> 6, d = e & 63;
            float4 f;
            f.x = tms[min(max(v.x, -16), 16) + 16];
            f.y = tms[min(max(v.y, -16), 16) + 16];
            f.z = tms[min(max(v.z, -16), 16) + 16];
            f.w = tms[min(max(v.w, -16), 16) + 16];
            *(float4*)&vbuf[j][d] = f;
        }
        __syncthreads();
        // prefetch next tile while computing (MLP over the 268MB rp stream)
        if (jt + 1 < 8) {
#pragma unroll
            for (int l = 0; l < 4; l++)
                pre[l] = src[(size_t)(jt + 1) * 1024 + tid + l * 256];
        }
        float acc0 = 0.f, acc1 = 0.f;
#pragma unroll
        for (int dq = 0; dq < 16; dq++) {
            float4 v4 = *(const float4*)&vbuf[jj][dq * 4];
            float4 qa = *(const float4*)&qs[h0][dq * 4];
            float4 qb = *(const float4*)&qs[h0 + 1][dq * 4];
            acc0 += v4.x * qa.x + v4.y * qa.y + v4.z * qa.z + v4.w * qa.w;
            acc1 += v4.x * qb.x + v4.y * qb.y + v4.z * qb.z + v4.w * qb.w;
        }
        s_row[h0][jt * 64 + jj] = acc0;
        s_row[h0 + 1][jt * 64 + jj] = acc1;
        __syncthreads();
    }

    // Softmax: warp w handles head w. 16 j's per lane.
    int w = tid >> 5, lane = tid & 31;
    float* grow = attn + (((size_t)(b * Hn + w)) * Sn + i) * Sn;
    float v[16];
    float mx = -3.0e38f;
#pragma unroll
    for (int k = 0; k < 16; k++) {
        int j = lane + k * 32;
        float x = grow[j] + s_row[w][j];
        if (mask_s[j] == 0) x = -1e9f;
        v[k] = x;
        mx = fmaxf(mx, x);
    }
#pragma unroll
    for (int off = 16; off; off >>= 1) mx = fmaxf(mx, __shfl_xor_sync(0xffffffffu, mx, off));
    float s = 0.f;
#pragma unroll
    for (int k = 0; k < 16; k++) { v[k] = __expf(v[k] - mx); s += v[k]; }
#pragma unroll
    for (int off = 16; off; off >>= 1) s += __shfl_xor_sync(0xffffffffu, s, off);
    float inv = 1.0f / s;
#pragma unroll
    for (int k = 0; k < 16; k++) grow[lane + k * 32] = v[k] * inv;
}

// ---------------------------------------------------------------------------
__global__ __launch_bounds__(256) void ln_kernel(const float* __restrict__ query,
                                                 const float* __restrict__ gamma,
                                                 const float* __restrict__ beta,
                                                 float* __restrict__ y)
{
    int row = blockIdx.x;
    int tid = threadIdx.x;
    size_t base = (size_t)row * Dn;
    float x0 = g_out[base + tid] + query[base + tid];
    float x1 = g_out[base + tid + 256] + query[base + tid + 256];
    float s = x0 + x1, sq = x0 * x0 + x1 * x1;
    __shared__ float r1[8], r2[8];
#pragma unroll
    for (int off = 16; off; off >>= 1) {
        s += __shfl_xor_sync(0xffffffffu, s, off);
        sq += __shfl_xor_sync(0xffffffffu, sq, off);
    }
    if ((tid & 31) == 0) { r1[tid >> 5] = s; r2[tid >> 5] = sq; }
    __syncthreads();
    s = 0.f; sq = 0.f;
#pragma unroll
    for (int w = 0; w < 8; w++) { s += r1[w]; sq += r2[w]; }
    float mean = s * (1.0f / Dn);
    float var = sq * (1.0f / Dn) - mean * mean;
    float rstd = rsqrtf(var + 1e-5f);
    y[base + tid]       = (x0 - mean) * rstd * gamma[tid] + beta[tid];
    y[base + tid + 256] = (x1 - mean) * rstd * gamma[tid + 256] + beta[tid + 256];
}

// ---------------------------------------------------------------------------
extern "C" void kernel_launch(void* const* d_in, const int* in_sizes, int n_in,
                              void* d_out, int out_size)
{
    (void)in_sizes; (void)n_in; (void)out_size;
    const float* query = (const float*)d_in[0];
    const float* key   = (const float*)d_in[1];
    const float* value = (const float*)d_in[2];
    const float* Wq = (const float*)d_in[3];
    const float* bq = (const float*)d_in[4];
    const float* Wk = (const float*)d_in[5];
    const float* bk = (const float*)d_in[6];
    const float* Wv = (const float*)d_in[7];
    const float* bv = (const float*)d_in[8];
    const float* Wo = (const float*)d_in[9];
    const float* bo = (const float*)d_in[10];
    const float* rel_table = (const float*)d_in[11];
    const float* gamma = (const float*)d_in[12];
    const float* beta  = (const float*)d_in[13];
    const int* mask = (const int*)d_in[14];
    const int* rp   = (const int*)d_in[15];

    float* y = (float*)d_out;                        // [B,S,D]
    float* attn = y + (size_t)Bn * Sn * Dn;          // [B,H,S,S]

    const int SMB = 2 * BUFW * 4;                    // 55296 bytes
    cudaFuncSetAttribute(tc_gemm, cudaFuncAttributeMaxDynamicSharedMemorySize, SMB);

    // fused QKV projections
    tc_gemm<<<dim3(8, 16, 3), 256, SMB>>>(query, key, value, Wq, Wk, Wv,
                                          bq, bk, bv, nullptr, 0, 512);
    // scores
    tc_gemm<<<dim3(8, 4, 32), 256, SMB>>>(nullptr, nullptr, nullptr, nullptr, nullptr, nullptr,
                                          nullptr, nullptr, nullptr, attn, 4, 64);
    // fused rel-pos bias + mask + softmax
    bias_softmax_kernel<<<dim3(Sn, Bn), 256>>>(rp, rel_table, mask, attn);
    // attn @ V
    tc_gemm<<<dim3(1, 4, 32), 256, SMB>>>(nullptr, nullptr, nullptr, nullptr, nullptr, nullptr,
                                          nullptr, nullptr, nullptr, attn, 5, 512);
    // out projection
    tc_gemm<<<dim3(8, 16, 1), 256, SMB>>>(nullptr, nullptr, nullptr, Wo, nullptr, nullptr,
                                          bo, nullptr, nullptr, nullptr, 3, 512);
    ln_kernel<<<Bn * Sn, 256>>>(query, gamma, beta, y);
}

// round 8
// speedup vs baseline: 3.7403x; 1.1975x over previous
#include <cuda_runtime.h>
#include <math.h>
#include <stdint.h>

#define Bn 4
#define Sn 512
#define Dn 512
#define Hn 8
#define DKn 64
#define NTAB 33

// Scratch (no allocations allowed -> __device__ globals)
__device__ float g_q[Bn*Hn*Sn*DKn];
__device__ float g_k[Bn*Hn*Sn*DKn];
__device__ float g_vT[Bn*Hn*DKn*Sn];   // V transposed: [b,h,dk,s]
__device__ float g_ctx[(size_t)Bn*Sn*Dn];
__device__ float g_out[(size_t)Bn*Sn*Dn];

__device__ __forceinline__ uint32_t to_tf32(float f) {
    uint32_t u;
    asm("cvt.rna.tf32.f32 %0, %1;" : "=r"(u) : "f"(f));
    return u;
}

__device__ __forceinline__ void mma_tf32(float* c, const uint32_t* a, const uint32_t* b) {
    asm volatile(
        "mma.sync.aligned.m16n8k8.row.col.f32.tf32.tf32.f32 "
        "{%0,%1,%2,%3}, {%4,%5,%6,%7}, {%8,%9}, {%0,%1,%2,%3};"
        : "+f"(c[0]), "+f"(c[1]), "+f"(c[2]), "+f"(c[3])
        : "r"(a[0]), "r"(a[1]), "r"(a[2]), "r"(a[3]), "r"(b[0]), "r"(b[1]));
}

// ===========================================================================
// Unified tensor-core tf32 GEMM: D[m,n] = sum_k A[m,k]*B[n,k]
// Template MT = M tile (128 or 64). N tile fixed 64. 256 threads.
// MT=128: warps 4(m)x2(n), warp tile 32x32. MT=64: warps 2(m)x4(n), 32x16.
// ===========================================================================
template<int MT>
__global__ __launch_bounds__(256) void tc_gemm(
    const float* __restrict__ A0, const float* __restrict__ A1, const float* __restrict__ A2,
    const float* __restrict__ B0, const float* __restrict__ B1, const float* __restrict__ B2,
    const float* __restrict__ bias0, const float* __restrict__ bias1, const float* __restrict__ bias2,
    float* __restrict__ attn, int mode, int kTot)
{
    constexpr int WMc = (MT == 128) ? 4 : 2;     // warps along m
    constexpr int WNc = 8 / WMc;                 // warps along n
    constexpr int NFR = 64 / (WNc * 8);          // n-frags per warp
    constexpr int AL  = MT / 32;                 // A float4 loads per thread
    constexpr int AWp = MT * 36;                 // A words per buffer
    constexpr int BUFWp = (MT + 64) * 36;

    extern __shared__ uint32_t smem_u[];
    int tid = threadIdx.x;
    int wid = tid >> 5, lane = tid & 31;
    int wm = wid % WMc, wn = wid / WMc;
    int g = lane >> 2, t4 = lane & 3;

    int row0 = blockIdx.y * MT;
    int n0   = blockIdx.x * 64;
    int bh   = blockIdx.z;

    const float* Ap; const float* Bp; const float* biasp = nullptr;
    int ldA, ldB, emode;
    if (mode == 0) {
        int w = bh;
        Ap = (w == 0) ? A0 : (w == 1) ? A1 : A2;
        Bp = (w == 0) ? B0 : (w == 1) ? B1 : B2;
        biasp = (w == 0) ? bias0 : (w == 1) ? bias1 : bias2;
        ldA = Dn; ldB = Dn; emode = w;
    } else if (mode == 3) {
        Ap = g_ctx; Bp = B0; biasp = bias0; ldA = Dn; ldB = Dn; emode = 3;
    } else if (mode == 4) {
        Ap = g_q + (size_t)bh * Sn * DKn;   // M = queries (i)
        Bp = g_k + (size_t)bh * Sn * DKn;   // N = keys (j)
        ldA = DKn; ldB = DKn; emode = 4;
    } else {
        Ap = attn + (size_t)bh * Sn * Sn;   // M = queries (i), K = j
        Bp = g_vT + (size_t)bh * DKn * Sn;  // N = d
        ldA = Sn; ldB = Sn; emode = 5;
    }
    Ap += (size_t)row0 * ldA;
    Bp += (size_t)n0 * ldB;

    float acc[2][NFR][4];
#pragma unroll
    for (int mi = 0; mi < 2; mi++)
#pragma unroll
        for (int ni = 0; ni < NFR; ni++)
#pragma unroll
            for (int q = 0; q < 4; q++) acc[mi][ni][q] = 0.f;

    float4 pa[AL], pb[2];
    {
        int r = tid >> 3, c4 = tid & 7;
#pragma unroll
        for (int l = 0; l < AL; l++)
            pa[l] = *(const float4*)(Ap + (size_t)(r + l * 32) * ldA + c4 * 4);
#pragma unroll
        for (int l = 0; l < 2; l++)
            pb[l] = *(const float4*)(Bp + (size_t)(r + l * 32) * ldB + c4 * 4);
    }
    {
        int r = tid >> 3, c4 = tid & 7;
        uint32_t* As = smem_u;
        uint32_t* Bs = smem_u + AWp;
#pragma unroll
        for (int l = 0; l < AL; l++) {
            uint32_t* d = As + (r + l * 32) * 36 + c4 * 4;
            d[0] = to_tf32(pa[l].x); d[1] = to_tf32(pa[l].y);
            d[2] = to_tf32(pa[l].z); d[3] = to_tf32(pa[l].w);
        }
#pragma unroll
        for (int l = 0; l < 2; l++) {
            uint32_t* d = Bs + (r + l * 32) * 36 + c4 * 4;
            d[0] = to_tf32(pb[l].x); d[1] = to_tf32(pb[l].y);
            d[2] = to_tf32(pb[l].z); d[3] = to_tf32(pb[l].w);
        }
    }
    __syncthreads();

    int nk = kTot / 32;
    for (int kc = 0; kc < nk; kc++) {
        if (kc + 1 < nk) {
            int k0 = (kc + 1) * 32;
            int r = tid >> 3, c4 = tid & 7;
#pragma unroll
            for (int l = 0; l < AL; l++)
                pa[l] = *(const float4*)(Ap + (size_t)(r + l * 32) * ldA + k0 + c4 * 4);
#pragma unroll
            for (int l = 0; l < 2; l++)
                pb[l] = *(const float4*)(Bp + (size_t)(r + l * 32) * ldB + k0 + c4 * 4);
        }
        const uint32_t* As = smem_u + (kc & 1) * BUFWp;
        const uint32_t* Bs = As + AWp;
#pragma unroll
        for (int kk = 0; kk < 4; kk++) {
            int kb = kk * 8 + t4;
            uint32_t a[2][4], b[NFR][2];
#pragma unroll
            for (int mi = 0; mi < 2; mi++) {
                int r = (wm * 32 + mi * 16 + g) * 36 + kb;
                a[mi][0] = As[r];
                a[mi][1] = As[r + 8 * 36];
                a[mi][2] = As[r + 4];
                a[mi][3] = As[r + 8 * 36 + 4];
            }
#pragma unroll
            for (int ni = 0; ni < NFR; ni++) {
                int r = (wn * (NFR * 8) + ni * 8 + g) * 36 + kb;
                b[ni][0] = Bs[r];
                b[ni][1] = Bs[r + 4];
            }
#pragma unroll
            for (int mi = 0; mi < 2; mi++)
#pragma unroll
                for (int ni = 0; ni < NFR; ni++)
                    mma_tf32(acc[mi][ni], a[mi], b[ni]);
        }
        if (kc + 1 < nk) {
            uint32_t* Aw = smem_u + ((kc + 1) & 1) * BUFWp;
            uint32_t* Bw = Aw + AWp;
            int r = tid >> 3, c4 = tid & 7;
#pragma unroll
            for (int l = 0; l < AL; l++) {
                uint32_t* d = Aw + (r + l * 32) * 36 + c4 * 4;
                d[0] = to_tf32(pa[l].x); d[1] = to_tf32(pa[l].y);
                d[2] = to_tf32(pa[l].z); d[3] = to_tf32(pa[l].w);
            }
#pragma unroll
            for (int l = 0; l < 2; l++) {
                uint32_t* d = Bw + (r + l * 32) * 36 + c4 * 4;
                d[0] = to_tf32(pb[l].x); d[1] = to_tf32(pb[l].y);
                d[2] = to_tf32(pb[l].z); d[3] = to_tf32(pb[l].w);
            }
            __syncthreads();
        }
    }

#pragma unroll
    for (int mi = 0; mi < 2; mi++) {
        int row = row0 + wm * 32 + mi * 16 + g;
#pragma unroll
        for (int ni = 0; ni < NFR; ni++) {
            int col = n0 + wn * (NFR * 8) + ni * 8 + 2 * t4;
            float v0 = acc[mi][ni][0], v1 = acc[mi][ni][1];
            float v2 = acc[mi][ni][2], v3 = acc[mi][ni][3];
            if (emode <= 3) {
                float b0v = biasp[col], b1v = biasp[col + 1];
                v0 += b0v; v1 += b1v; v2 += b0v; v3 += b1v;
            }
            if (emode <= 2) {
                int b = row >> 9, s = row & 511;
                int h = col >> 6, dk = col & 63;
                if (emode == 0) {
                    float* p = g_q + (((size_t)(b * Hn + h)) * Sn + s) * DKn + dk;
                    *(float2*)p = make_float2(v0, v1);
                    *(float2*)(p + 8 * DKn) = make_float2(v2, v3);
                } else if (emode == 1) {
                    float* p = g_k + (((size_t)(b * Hn + h)) * Sn + s) * DKn + dk;
                    *(float2*)p = make_float2(v0, v1);
                    *(float2*)(p + 8 * DKn) = make_float2(v2, v3);
                } else {
                    float* p = g_vT + (((size_t)(b * Hn + h)) * DKn + dk) * Sn + s;
                    p[0] = v0; p[Sn] = v1; p[8] = v2; p[Sn + 8] = v3;
                }
            } else if (emode == 3) {
                float* p = g_out + (size_t)row * Dn + col;
                *(float2*)p = make_float2(v0, v1);
                *(float2*)(p + 8 * Dn) = make_float2(v2, v3);
            } else if (emode == 4) {
                float* p = attn + ((size_t)bh * Sn + row) * Sn + col;
                *(float2*)p = make_float2(v0 * 0.125f, v1 * 0.125f);
                *(float2*)(p + 8 * Sn) = make_float2(v2 * 0.125f, v3 * 0.125f);
            } else {
                int b = bh >> 3, h = bh & 7;
                float* p = g_ctx + ((size_t)b * Sn + row) * Dn + h * DKn + col;
                *(float2*)p = make_float2(v0, v1);
                *(float2*)(p + 8 * Dn) = make_float2(v2, v3);
            }
        }
    }
}

// ===========================================================================
// Fused relative-position bias + mask + softmax, bias dot via mma.sync tf32.
// One block per (b,i). Bias per tile: D[j=64, h=8] = vbuf[64x64] @ qs[8x64]^T.
// Warps 0-3 handle even jt tile, 4-7 odd tile (each warp: 16 j rows, 8 MMAs).
// ===========================================================================
__global__ __launch_bounds__(256) void bias_softmax_kernel(
    const int* __restrict__ rp, const float* __restrict__ rel_table,
    const int* __restrict__ mask, float* __restrict__ attn)
{
    __shared__ __align__(16) uint32_t qs_p[8 * 68];        // tf32 bits, B operand
    __shared__ __align__(16) uint32_t vbuf[2][64 * 68];    // tf32 bits, A operand
    __shared__ __align__(16) float s_row[8][Sn];
    __shared__ float tms[NTAB + 3];
    __shared__ int mask_s[Sn];

    int i = blockIdx.x;
    int b = blockIdx.y;
    int tid = threadIdx.x;
    int wid = tid >> 5, lane = tid & 31;
    int g = lane >> 2, t4 = lane & 3;
    int half = wid >> 2;       // which jt tile of the pair
    int jq = wid & 3;          // 16-row j slice

    if (tid < NTAB) {
        float s = 0.f;
#pragma unroll
        for (int e = 0; e < DKn; e++) s += rel_table[tid * DKn + e];
        tms[tid] = __uint_as_float(to_tf32(s * (1.0f / DKn)));
    }
    for (int l = tid; l < Hn * DKn; l += 256) {
        int h = l >> 6, d = l & 63;
        qs_p[h * 68 + d] = to_tf32(g_q[(((size_t)b * Hn + h) * Sn + i) * DKn + d]);
    }
    {
        mask_s[tid] = mask[b * Sn + tid];
        mask_s[tid + 256] = mask[b * Sn + tid + 256];
    }

    const int4* src = (const int4*)(rp + (((size_t)b * Sn + i) * Sn) * DKn);

    int4 pre[8];               // two 64x64 tiles in flight
#pragma unroll
    for (int l = 0; l < 8; l++) pre[l] = src[tid + l * 256];
    __syncthreads();

    for (int jt2 = 0; jt2 < 4; jt2++) {
        // gather pair of tiles into vbuf (tf32 table values)
#pragma unroll
        for (int l = 0; l < 8; l++) {
            int tsel = l >> 2;
            int q4 = tid + (l & 3) * 256;
            int4 v = pre[l];
            int e = q4 * 4;
            int j = e >> 6, d = e & 63;
            float4 f;
            f.x = tms[min(max(v.x, -16), 16) + 16];
            f.y = tms[min(max(v.y, -16), 16) + 16];
            f.z = tms[min(max(v.z, -16), 16) + 16];
            f.w = tms[min(max(v.w, -16), 16) + 16];
            *(float4*)&vbuf[tsel][j * 68 + d] = f;
        }
        __syncthreads();
        // prefetch next pair while MMAs run
        if (jt2 + 1 < 4) {
#pragma unroll
            for (int l = 0; l < 8; l++)
                pre[l] = src[(size_t)(jt2 + 1) * 2048 + tid + l * 256];
        }
        // bias GEMM: this warp's 16 j rows x 8 heads, K=64
        const uint32_t* Vb = vbuf[half];
        float c[4] = {0.f, 0.f, 0.f, 0.f};
#pragma unroll
        for (int kk = 0; kk < 8; kk++) {
            int kb = kk * 8 + t4;
            uint32_t a[4], bb[2];
            int r = (jq * 16 + g) * 68 + kb;
            a[0] = Vb[r];
            a[1] = Vb[r + 8 * 68];
            a[2] = Vb[r + 4];
            a[3] = Vb[r + 8 * 68 + 4];
            bb[0] = qs_p[g * 68 + kb];
            bb[1] = qs_p[g * 68 + kb + 4];
            mma_tf32(c, a, bb);
        }
        // c0=D[g][2t4], c1=D[g][2t4+1], c2=D[g+8][2t4], c3=D[g+8][2t4+1]
        int jbase = (jt2 * 2 + half) * 64 + jq * 16;
        s_row[2 * t4][jbase + g] = c[0];
        s_row[2 * t4 + 1][jbase + g] = c[1];
        s_row[2 * t4][jbase + g + 8] = c[2];
        s_row[2 * t4 + 1][jbase + g + 8] = c[3];
        __syncthreads();
    }

    // Softmax: warp w handles head w. 16 j's per lane.
    float* grow = attn + (((size_t)(b * Hn + wid)) * Sn + i) * Sn;
    float v[16];
    float mx = -3.0e38f;
#pragma unroll
    for (int k = 0; k < 16; k++) {
        int j = lane + k * 32;
        float x = grow[j] + s_row[wid][j];
        if (mask_s[j] == 0) x = -1e9f;
        v[k] = x;
        mx = fmaxf(mx, x);
    }
#pragma unroll
    for (int off = 16; off; off >>= 1) mx = fmaxf(mx, __shfl_xor_sync(0xffffffffu, mx, off));
    float s = 0.f;
#pragma unroll
    for (int k = 0; k < 16; k++) { v[k] = __expf(v[k] - mx); s += v[k]; }
#pragma unroll
    for (int off = 16; off; off >>= 1) s += __shfl_xor_sync(0xffffffffu, s, off);
    float inv = 1.0f / s;
#pragma unroll
    for (int k = 0; k < 16; k++) grow[lane + k * 32] = v[k] * inv;
}

// ---------------------------------------------------------------------------
__global__ __launch_bounds__(256) void ln_kernel(const float* __restrict__ query,
                                                 const float* __restrict__ gamma,
                                                 const float* __restrict__ beta,
                                                 float* __restrict__ y)
{
    int row = blockIdx.x;
    int tid = threadIdx.x;
    size_t base = (size_t)row * Dn;
    float x0 = g_out[base + tid] + query[base + tid];
    float x1 = g_out[base + tid + 256] + query[base + tid + 256];
    float s = x0 + x1, sq = x0 * x0 + x1 * x1;
    __shared__ float r1[8], r2[8];
#pragma unroll
    for (int off = 16; off; off >>= 1) {
        s += __shfl_xor_sync(0xffffffffu, s, off);
        sq += __shfl_xor_sync(0xffffffffu, sq, off);
    }
    if ((tid & 31) == 0) { r1[tid >> 5] = s; r2[tid >> 5] = sq; }
    __syncthreads();
    s = 0.f; sq = 0.f;
#pragma unroll
    for (int w = 0; w < 8; w++) { s += r1[w]; sq += r2[w]; }
    float mean = s * (1.0f / Dn);
    float var = sq * (1.0f / Dn) - mean * mean;
    float rstd = rsqrtf(var + 1e-5f);
    y[base + tid]       = (x0 - mean) * rstd * gamma[tid] + beta[tid];
    y[base + tid + 256] = (x1 - mean) * rstd * gamma[tid + 256] + beta[tid + 256];
}

// ---------------------------------------------------------------------------
extern "C" void kernel_launch(void* const* d_in, const int* in_sizes, int n_in,
                              void* d_out, int out_size)
{
    (void)in_sizes; (void)n_in; (void)out_size;
    const float* query = (const float*)d_in[0];
    const float* key   = (const float*)d_in[1];
    const float* value = (const float*)d_in[2];
    const float* Wq = (const float*)d_in[3];
    const float* bq = (const float*)d_in[4];
    const float* Wk = (const float*)d_in[5];
    const float* bk = (const float*)d_in[6];
    const float* Wv = (const float*)d_in[7];
    const float* bv = (const float*)d_in[8];
    const float* Wo = (const float*)d_in[9];
    const float* bo = (const float*)d_in[10];
    const float* rel_table = (const float*)d_in[11];
    const float* gamma = (const float*)d_in[12];
    const float* beta  = (const float*)d_in[13];
    const int* mask = (const int*)d_in[14];
    const int* rp   = (const int*)d_in[15];

    float* y = (float*)d_out;                        // [B,S,D]
    float* attn = y + (size_t)Bn * Sn * Dn;          // [B,H,S,S]

    const int SMB128 = 2 * (128 + 64) * 36 * 4;      // 55296
    const int SMB64  = 2 * (64 + 64) * 36 * 4;       // 36864
    cudaFuncSetAttribute(tc_gemm<128>, cudaFuncAttributeMaxDynamicSharedMemorySize, SMB128);
    cudaFuncSetAttribute(tc_gemm<64>,  cudaFuncAttributeMaxDynamicSharedMemorySize, SMB64);

    // fused QKV projections
    tc_gemm<128><<<dim3(8, 16, 3), 256, SMB128>>>(query, key, value, Wq, Wk, Wv,
                                                  bq, bk, bv, nullptr, 0, 512);
    // scores
    tc_gemm<128><<<dim3(8, 4, 32), 256, SMB128>>>(nullptr, nullptr, nullptr, nullptr, nullptr, nullptr,
                                                  nullptr, nullptr, nullptr, attn, 4, 64);
    // fused rel-pos bias + mask + softmax (bias via mma)
    bias_softmax_kernel<<<dim3(Sn, Bn), 256>>>(rp, rel_table, mask, attn);
    // attn @ V  (MT=64 -> 256 CTAs)
    tc_gemm<64><<<dim3(1, 8, 32), 256, SMB64>>>(nullptr, nullptr, nullptr, nullptr, nullptr, nullptr,
                                                nullptr, nullptr, nullptr, attn, 5, 512);
    // out projection (MT=64 -> 256 CTAs)
    tc_gemm<64><<<dim3(8, 32, 1), 256, SMB64>>>(nullptr, nullptr, nullptr, Wo, nullptr, nullptr,
                                                bo, nullptr, nullptr, nullptr, 3, 512);
    ln_kernel<<<Bn * Sn, 256>>>(query, gamma, beta, y);
}

// round 9
// speedup vs baseline: 3.9345x; 1.0519x over previous
#include <cuda_runtime.h>
#include <math.h>
#include <stdint.h>

#define Bn 4
#define Sn 512
#define Dn 512
#define Hn 8
#define DKn 64
#define NTAB 33
#define CTXSZ ((size_t)Bn*Sn*Dn)   // 1048576 floats

// Scratch (no allocations allowed -> __device__ globals)
__device__ float g_q[Bn*Hn*Sn*DKn];
__device__ float g_k[Bn*Hn*Sn*DKn];
__device__ float g_vT[Bn*Hn*DKn*Sn];     // V transposed: [b,h,dk,s]
__device__ float g_ctx[4 * (size_t)Bn*Sn*Dn];  // 4 split-K partials
__device__ float g_out[(size_t)Bn*Sn*Dn];

__device__ __forceinline__ uint32_t to_tf32(float f) {
    uint32_t u;
    asm("cvt.rna.tf32.f32 %0, %1;" : "=r"(u) : "f"(f));
    return u;
}

__device__ __forceinline__ void mma_tf32(float* c, const uint32_t* a, const uint32_t* b) {
    asm volatile(
        "mma.sync.aligned.m16n8k8.row.col.f32.tf32.tf32.f32 "
        "{%0,%1,%2,%3}, {%4,%5,%6,%7}, {%8,%9}, {%0,%1,%2,%3};"
        : "+f"(c[0]), "+f"(c[1]), "+f"(c[2]), "+f"(c[3])
        : "r"(a[0]), "r"(a[1]), "r"(a[2]), "r"(a[3]), "r"(b[0]), "r"(b[1]));
}

// float4 load; when sum4 set, sums the same offset across the 4 ctx partials.
__device__ __forceinline__ float4 ld_sum4(const float* p, bool sum4) {
    float4 v = *(const float4*)p;
    if (sum4) {
        const float* q = p;
#pragma unroll
        for (int s = 1; s < 4; s++) {
            q += CTXSZ;
            float4 w = *(const float4*)q;
            v.x += w.x; v.y += w.y; v.z += w.z; v.w += w.w;
        }
    }
    return v;
}

// ===========================================================================
// Unified tensor-core tf32 GEMM: D[m,n] = sum_k A[m,k]*B[n,k]
//  mode 0/1/2 (z picks Q/K/V): proj; mode 3: out-proj (A = sum of ctx partials)
//  mode 4: scores; mode 5: attn*V split-K (z = bh*4+split, K=128 per split,
//          writes partial ctx buffer `split`)
// Template MT = M tile (128 or 64). N tile fixed 64. 256 threads.
// ===========================================================================
template<int MT>
__global__ __launch_bounds__(256) void tc_gemm(
    const float* __restrict__ A0, const float* __restrict__ A1, const float* __restrict__ A2,
    const float* __restrict__ B0, const float* __restrict__ B1, const float* __restrict__ B2,
    const float* __restrict__ bias0, const float* __restrict__ bias1, const float* __restrict__ bias2,
    float* __restrict__ attn, int mode, int kTot)
{
    constexpr int WMc = (MT == 128) ? 4 : 2;
    constexpr int WNc = 8 / WMc;
    constexpr int NFR = 64 / (WNc * 8);
    constexpr int AL  = MT / 32;
    constexpr int AWp = MT * 36;
    constexpr int BUFWp = (MT + 64) * 36;

    extern __shared__ uint32_t smem_u[];
    int tid = threadIdx.x;
    int wid = tid >> 5, lane = tid & 31;
    int wm = wid % WMc, wn = wid / WMc;
    int g = lane >> 2, t4 = lane & 3;

    int row0 = blockIdx.y * MT;
    int n0   = blockIdx.x * 64;
    int bh   = blockIdx.z;

    const float* Ap; const float* Bp; const float* biasp = nullptr;
    int ldA, ldB, emode, split = 0;
    if (mode == 0) {
        int w = bh;
        Ap = (w == 0) ? A0 : (w == 1) ? A1 : A2;
        Bp = (w == 0) ? B0 : (w == 1) ? B1 : B2;
        biasp = (w == 0) ? bias0 : (w == 1) ? bias1 : bias2;
        ldA = Dn; ldB = Dn; emode = w;
    } else if (mode == 3) {
        Ap = g_ctx; Bp = B0; biasp = bias0; ldA = Dn; ldB = Dn; emode = 3;
    } else if (mode == 4) {
        Ap = g_q + (size_t)bh * Sn * DKn;   // M = queries (i)
        Bp = g_k + (size_t)bh * Sn * DKn;   // N = keys (j)
        ldA = DKn; ldB = DKn; emode = 4;
    } else {
        split = bh & 3; bh >>= 2;
        Ap = attn + (size_t)bh * Sn * Sn + split * 128;   // K offset
        Bp = g_vT + (size_t)bh * DKn * Sn + split * 128;
        ldA = Sn; ldB = Sn; emode = 5;
    }
    Ap += (size_t)row0 * ldA;
    Bp += (size_t)n0 * ldB;
    const bool sumA = (mode == 3);

    float acc[2][NFR][4];
#pragma unroll
    for (int mi = 0; mi < 2; mi++)
#pragma unroll
        for (int ni = 0; ni < NFR; ni++)
#pragma unroll
            for (int q = 0; q < 4; q++) acc[mi][ni][q] = 0.f;

    float4 pa[AL], pb[2];
    {
        int r = tid >> 3, c4 = tid & 7;
#pragma unroll
        for (int l = 0; l < AL; l++)
            pa[l] = ld_sum4(Ap + (size_t)(r + l * 32) * ldA + c4 * 4, sumA);
#pragma unroll
        for (int l = 0; l < 2; l++)
            pb[l] = *(const float4*)(Bp + (size_t)(r + l * 32) * ldB + c4 * 4);
    }
    {
        int r = tid >> 3, c4 = tid & 7;
        uint32_t* As = smem_u;
        uint32_t* Bs = smem_u + AWp;
#pragma unroll
        for (int l = 0; l < AL; l++) {
            uint32_t* d = As + (r + l * 32) * 36 + c4 * 4;
            d[0] = to_tf32(pa[l].x); d[1] = to_tf32(pa[l].y);
            d[2] = to_tf32(pa[l].z); d[3] = to_tf32(pa[l].w);
        }
#pragma unroll
        for (int l = 0; l < 2; l++) {
            uint32_t* d = Bs + (r + l * 32) * 36 + c4 * 4;
            d[0] = to_tf32(pb[l].x); d[1] = to_tf32(pb[l].y);
            d[2] = to_tf32(pb[l].z); d[3] = to_tf32(pb[l].w);
        }
    }
    __syncthreads();

    int nk = kTot / 32;
    for (int kc = 0; kc < nk; kc++) {
        if (kc + 1 < nk) {
            int k0 = (kc + 1) * 32;
            int r = tid >> 3, c4 = tid & 7;
#pragma unroll
            for (int l = 0; l < AL; l++)
                pa[l] = ld_sum4(Ap + (size_t)(r + l * 32) * ldA + k0 + c4 * 4, sumA);
#pragma unroll
            for (int l = 0; l < 2; l++)
                pb[l] = *(const float4*)(Bp + (size_t)(r + l * 32) * ldB + k0 + c4 * 4);
        }
        const uint32_t* As = smem_u + (kc & 1) * BUFWp;
        const uint32_t* Bs = As + AWp;
#pragma unroll
        for (int kk = 0; kk < 4; kk++) {
            int kb = kk * 8 + t4;
            uint32_t a[2][4], b[NFR][2];
#pragma unroll
            for (int mi = 0; mi < 2; mi++) {
                int r = (wm * 32 + mi * 16 + g) * 36 + kb;
                a[mi][0] = As[r];
                a[mi][1] = As[r + 8 * 36];
                a[mi][2] = As[r + 4];
                a[mi][3] = As[r + 8 * 36 + 4];
            }
#pragma unroll
            for (int ni = 0; ni < NFR; ni++) {
                int r = (wn * (NFR * 8) + ni * 8 + g) * 36 + kb;
                b[ni][0] = Bs[r];
                b[ni][1] = Bs[r + 4];
            }
#pragma unroll
            for (int mi = 0; mi < 2; mi++)
#pragma unroll
                for (int ni = 0; ni < NFR; ni++)
                    mma_tf32(acc[mi][ni], a[mi], b[ni]);
        }
        if (kc + 1 < nk) {
            uint32_t* Aw = smem_u + ((kc + 1) & 1) * BUFWp;
            uint32_t* Bw = Aw + AWp;
            int r = tid >> 3, c4 = tid & 7;
#pragma unroll
            for (int l = 0; l < AL; l++) {
                uint32_t* d = Aw + (r + l * 32) * 36 + c4 * 4;
                d[0] = to_tf32(pa[l].x); d[1] = to_tf32(pa[l].y);
                d[2] = to_tf32(pa[l].z); d[3] = to_tf32(pa[l].w);
            }
#pragma unroll
            for (int l = 0; l < 2; l++) {
                uint32_t* d = Bw + (r + l * 32) * 36 + c4 * 4;
                d[0] = to_tf32(pb[l].x); d[1] = to_tf32(pb[l].y);
                d[2] = to_tf32(pb[l].z); d[3] = to_tf32(pb[l].w);
            }
            __syncthreads();
        }
    }

#pragma unroll
    for (int mi = 0; mi < 2; mi++) {
        int row = row0 + wm * 32 + mi * 16 + g;
#pragma unroll
        for (int ni = 0; ni < NFR; ni++) {
            int col = n0 + wn * (NFR * 8) + ni * 8 + 2 * t4;
            float v0 = acc[mi][ni][0], v1 = acc[mi][ni][1];
            float v2 = acc[mi][ni][2], v3 = acc[mi][ni][3];
            if (emode <= 3) {
                float b0v = biasp[col], b1v = biasp[col + 1];
                v0 += b0v; v1 += b1v; v2 += b0v; v3 += b1v;
            }
            if (emode <= 2) {
                int b = row >> 9, s = row & 511;
                int h = col >> 6, dk = col & 63;
                if (emode == 0) {
                    float* p = g_q + (((size_t)(b * Hn + h)) * Sn + s) * DKn + dk;
                    *(float2*)p = make_float2(v0, v1);
                    *(float2*)(p + 8 * DKn) = make_float2(v2, v3);
                } else if (emode == 1) {
                    float* p = g_k + (((size_t)(b * Hn + h)) * Sn + s) * DKn + dk;
                    *(float2*)p = make_float2(v0, v1);
                    *(float2*)(p + 8 * DKn) = make_float2(v2, v3);
                } else {
                    float* p = g_vT + (((size_t)(b * Hn + h)) * DKn + dk) * Sn + s;
                    p[0] = v0; p[Sn] = v1; p[8] = v2; p[Sn + 8] = v3;
                }
            } else if (emode == 3) {
                float* p = g_out + (size_t)row * Dn + col;
                *(float2*)p = make_float2(v0, v1);
                *(float2*)(p + 8 * Dn) = make_float2(v2, v3);
            } else if (emode == 4) {
                float* p = attn + ((size_t)bh * Sn + row) * Sn + col;
                *(float2*)p = make_float2(v0 * 0.125f, v1 * 0.125f);
                *(float2*)(p + 8 * Sn) = make_float2(v2 * 0.125f, v3 * 0.125f);
            } else {
                int b = bh >> 3, h = bh & 7;
                float* p = g_ctx + (size_t)split * CTXSZ
                         + ((size_t)b * Sn + row) * Dn + h * DKn + col;
                *(float2*)p = make_float2(v0, v1);
                *(float2*)(p + 8 * Dn) = make_float2(v2, v3);
            }
        }
    }
}

// ===========================================================================
// Fused relative-position bias + mask + softmax, bias dot via mma.sync tf32.
// ===========================================================================
__global__ __launch_bounds__(256) void bias_softmax_kernel(
    const int* __restrict__ rp, const float* __restrict__ rel_table,
    const int* __restrict__ mask, float* __restrict__ attn)
{
    __shared__ __align__(16) uint32_t qs_p[8 * 68];
    __shared__ __align__(16) uint32_t vbuf[2][64 * 68];
    __shared__ __align__(16) float s_row[8][Sn];
    __shared__ float tms[NTAB + 3];
    __shared__ int mask_s[Sn];

    int i = blockIdx.x;
    int b = blockIdx.y;
    int tid = threadIdx.x;
    int wid = tid >> 5, lane = tid & 31;
    int g = lane >> 2, t4 = lane & 3;
    int half = wid >> 2;
    int jq = wid & 3;

    if (tid < NTAB) {
        float s = 0.f;
#pragma unroll
        for (int e = 0; e < DKn; e++) s += rel_table[tid * DKn + e];
        tms[tid] = __uint_as_float(to_tf32(s * (1.0f / DKn)));
    }
    for (int l = tid; l < Hn * DKn; l += 256) {
        int h = l >> 6, d = l & 63;
        qs_p[h * 68 + d] = to_tf32(g_q[(((size_t)b * Hn + h) * Sn + i) * DKn + d]);
    }
    {
        mask_s[tid] = mask[b * Sn + tid];
        mask_s[tid + 256] = mask[b * Sn + tid + 256];
    }

    const int4* src = (const int4*)(rp + (((size_t)b * Sn + i) * Sn) * DKn);

    int4 pre[8];
#pragma unroll
    for (int l = 0; l < 8; l++) pre[l] = src[tid + l * 256];
    __syncthreads();

    for (int jt2 = 0; jt2 < 4; jt2++) {
#pragma unroll
        for (int l = 0; l < 8; l++) {
            int tsel = l >> 2;
            int q4 = tid + (l & 3) * 256;
            int4 v = pre[l];
            int e = q4 * 4;
            int j = e >> 6, d = e & 63;
            float4 f;
            f.x = tms[min(max(v.x, -16), 16) + 16];
            f.y = tms[min(max(v.y, -16), 16) + 16];
            f.z = tms[min(max(v.z, -16), 16) + 16];
            f.w = tms[min(max(v.w, -16), 16) + 16];
            *(float4*)&vbuf[tsel][j * 68 + d] = f;
        }
        __syncthreads();
        if (jt2 + 1 < 4) {
#pragma unroll
            for (int l = 0; l < 8; l++)
                pre[l] = src[(size_t)(jt2 + 1) * 2048 + tid + l * 256];
        }
        const uint32_t* Vb = vbuf[half];
        float c[4] = {0.f, 0.f, 0.f, 0.f};
#pragma unroll
        for (int kk = 0; kk < 8; kk++) {
            int kb = kk * 8 + t4;
            uint32_t a[4], bb[2];
            int r = (jq * 16 + g) * 68 + kb;
            a[0] = Vb[r];
            a[1] = Vb[r + 8 * 68];
            a[2] = Vb[r + 4];
            a[3] = Vb[r + 8 * 68 + 4];
            bb[0] = qs_p[g * 68 + kb];
            bb[1] = qs_p[g * 68 + kb + 4];
            mma_tf32(c, a, bb);
        }
        int jbase = (jt2 * 2 + half) * 64 + jq * 16;
        s_row[2 * t4][jbase + g] = c[0];
        s_row[2 * t4 + 1][jbase + g] = c[1];
        s_row[2 * t4][jbase + g + 8] = c[2];
        s_row[2 * t4 + 1][jbase + g + 8] = c[3];
        __syncthreads();
    }

    float* grow = attn + (((size_t)(b * Hn + wid)) * Sn + i) * Sn;
    float v[16];
    float mx = -3.0e38f;
#pragma unroll
    for (int k = 0; k < 16; k++) {
        int j = lane + k * 32;
        float x = grow[j] + s_row[wid][j];
        if (mask_s[j] == 0) x = -1e9f;
        v[k] = x;
        mx = fmaxf(mx, x);
    }
#pragma unroll
    for (int off = 16; off; off >>= 1) mx = fmaxf(mx, __shfl_xor_sync(0xffffffffu, mx, off));
    float s = 0.f;
#pragma unroll
    for (int k = 0; k < 16; k++) { v[k] = __expf(v[k] - mx); s += v[k]; }
#pragma unroll
    for (int off = 16; off; off >>= 1) s += __shfl_xor_sync(0xffffffffu, s, off);
    float inv = 1.0f / s;
#pragma unroll
    for (int k = 0; k < 16; k++) grow[lane + k * 32] = v[k] * inv;
}

// ---------------------------------------------------------------------------
__global__ __launch_bounds__(256) void ln_kernel(const float* __restrict__ query,
                                                 const float* __restrict__ gamma,
                                                 const float* __restrict__ beta,
                                                 float* __restrict__ y)
{
    int row = blockIdx.x;
    int tid = threadIdx.x;
    size_t base = (size_t)row * Dn;
    float x0 = g_out[base + tid] + query[base + tid];
    float x1 = g_out[base + tid + 256] + query[base + tid + 256];
    float s = x0 + x1, sq = x0 * x0 + x1 * x1;
    __shared__ float r1[8], r2[8];
#pragma unroll
    for (int off = 16; off; off >>= 1) {
        s += __shfl_xor_sync(0xffffffffu, s, off);
        sq += __shfl_xor_sync(0xffffffffu, sq, off);
    }
    if ((tid & 31) == 0) { r1[tid >> 5] = s; r2[tid >> 5] = sq; }
    __syncthreads();
    s = 0.f; sq = 0.f;
#pragma unroll
    for (int w = 0; w < 8; w++) { s += r1[w]; sq += r2[w]; }
    float mean = s * (1.0f / Dn);
    float var = sq * (1.0f / Dn) - mean * mean;
    float rstd = rsqrtf(var + 1e-5f);
    y[base + tid]       = (x0 - mean) * rstd * gamma[tid] + beta[tid];
    y[base + tid + 256] = (x1 - mean) * rstd * gamma[tid + 256] + beta[tid + 256];
}

// ---------------------------------------------------------------------------
extern "C" void kernel_launch(void* const* d_in, const int* in_sizes, int n_in,
                              void* d_out, int out_size)
{
    (void)in_sizes; (void)n_in; (void)out_size;
    const float* query = (const float*)d_in[0];
    const float* key   = (const float*)d_in[1];
    const float* value = (const float*)d_in[2];
    const float* Wq = (const float*)d_in[3];
    const float* bq = (const float*)d_in[4];
    const float* Wk = (const float*)d_in[5];
    const float* bk = (const float*)d_in[6];
    const float* Wv = (const float*)d_in[7];
    const float* bv = (const float*)d_in[8];
    const float* Wo = (const float*)d_in[9];
    const float* bo = (const float*)d_in[10];
    const float* rel_table = (const float*)d_in[11];
    const float* gamma = (const float*)d_in[12];
    const float* beta  = (const float*)d_in[13];
    const int* mask = (const int*)d_in[14];
    const int* rp   = (const int*)d_in[15];

    float* y = (float*)d_out;                        // [B,S,D]
    float* attn = y + (size_t)Bn * Sn * Dn;          // [B,H,S,S]

    const int SMB128 = 2 * (128 + 64) * 36 * 4;      // 55296
    const int SMB64  = 2 * (64 + 64) * 36 * 4;       // 36864
    cudaFuncSetAttribute(tc_gemm<128>, cudaFuncAttributeMaxDynamicSharedMemorySize, SMB128);
    cudaFuncSetAttribute(tc_gemm<64>,  cudaFuncAttributeMaxDynamicSharedMemorySize, SMB64);

    // fused QKV projections
    tc_gemm<128><<<dim3(8, 16, 3), 256, SMB128>>>(query, key, value, Wq, Wk, Wv,
                                                  bq, bk, bv, nullptr, 0, 512);
    // scores
    tc_gemm<128><<<dim3(8, 4, 32), 256, SMB128>>>(nullptr, nullptr, nullptr, nullptr, nullptr, nullptr,
                                                  nullptr, nullptr, nullptr, attn, 4, 64);
    // fused rel-pos bias + mask + softmax (bias via mma)
    bias_softmax_kernel<<<dim3(Sn, Bn), 256>>>(rp, rel_table, mask, attn);
    // attn @ V  split-K x4 -> 1024 CTAs, each K=128, writes partial ctx buffer
    tc_gemm<64><<<dim3(1, 8, 128), 256, SMB64>>>(nullptr, nullptr, nullptr, nullptr, nullptr, nullptr,
                                                 nullptr, nullptr, nullptr, attn, 5, 128);
    // out projection (A = sum of 4 ctx partials during load)
    tc_gemm<64><<<dim3(8, 32, 1), 256, SMB64>>>(nullptr, nullptr, nullptr, Wo, nullptr, nullptr,
                                                bo, nullptr, nullptr, nullptr, 3, 512);
    ln_kernel<<<Bn * Sn, 256>>>(query, gamma, beta, y);
}